// round 14
// baseline (speedup 1.0000x reference)
#include <cuda_runtime.h>
#include <cuda_bf16.h>
#include <stdint.h>
#include <math.h>

#define NB 64
#define NN 1024
#define NCH 256
#define NR 4
#define NK 1024
#define TOTB 10240
#define PADB 10248
#define EPSF 0.25f
#define P2M  0.1f
#define CCAP 128
#define FMAXV 3.402823466e+38f

#define OFF_HHAT   0LL
#define OFF_ZQ     16777216LL
#define OFF_IND    33554432LL
#define OFF_IDXHAT 33619968LL
#define OFF_VQ     33685504LL
#define OFF_LOGITS 33685505LL
#define OFF_PROBS  33686273LL
#define OFF_MODE   33687041LL

__device__ int     g_expert[NB];
__device__ int     g_phy[NB];
__device__ float   g_std;
__device__ float   g_zsq[NB * NN];
__device__ float   g_cbsq[NR * NK];
__device__ int     g_indices[NB * NN];
__device__ uint8_t g_bits[NB * PADB];
__device__ double  g_ssep[8192];
__device__ __align__(16) __nv_bfloat16 g_Hb[NB * NN * NCH];
__device__ __align__(16) __nv_bfloat16 g_cbb[NR * NK * NCH];
__device__ int   g_cand[(size_t)NB * NN * CCAP];
__device__ float g_candd[(size_t)NB * NN * CCAP];
__device__ int   g_cc[NB * NN];

// ---- helpers ----
__device__ __forceinline__ uint32_t smem_to_u32(const void* p) {
    uint32_t a;
    asm("{ .reg .u64 t; cvta.to.shared.u64 t, %1; cvt.u32.u64 %0, t; }" : "=r"(a) : "l"(p));
    return a;
}
__device__ __forceinline__ void ldmx4(uint32_t* r, uint32_t addr) {
    asm volatile("ldmatrix.sync.aligned.m8n8.x4.shared.b16 {%0,%1,%2,%3}, [%4];"
        : "=r"(r[0]), "=r"(r[1]), "=r"(r[2]), "=r"(r[3]) : "r"(addr));
}
__device__ __forceinline__ void mma_bf16(float* c, const uint32_t* a, const uint32_t* b) {
    asm volatile("mma.sync.aligned.m16n8k16.row.col.f32.bf16.bf16.f32 "
        "{%0,%1,%2,%3}, {%4,%5,%6,%7}, {%8,%9}, {%0,%1,%2,%3};"
        : "+f"(c[0]), "+f"(c[1]), "+f"(c[2]), "+f"(c[3])
        : "r"(a[0]), "r"(a[1]), "r"(a[2]), "r"(a[3]), "r"(b[0]), "r"(b[1]));
}
__device__ __forceinline__ void cp16(uint32_t dst, const void* src) {
    asm volatile("cp.async.cg.shared.global [%0], [%1], 16;" :: "r"(dst), "l"(src));
}

// ---- threefry (JAX) ----
__device__ __forceinline__ uint32_t rotl32(uint32_t x, int r) { return (x << r) | (x >> (32 - r)); }
__device__ __forceinline__ void threefry2x32(uint32_t k0, uint32_t k1, uint32_t x0, uint32_t x1,
                                             uint32_t& o0, uint32_t& o1) {
    uint32_t k2 = k0 ^ k1 ^ 0x1BD11BDAu;
    x0 += k0; x1 += k1;
#define TF_R(a) x0 += x1; x1 = rotl32(x1, a); x1 ^= x0;
#define TF_G(a,b,c,d) TF_R(a) TF_R(b) TF_R(c) TF_R(d)
    TF_G(13, 15, 26, 6)  x0 += k1; x1 += k2 + 1u;
    TF_G(17, 29, 16, 24) x0 += k2; x1 += k0 + 2u;
    TF_G(13, 15, 26, 6)  x0 += k0; x1 += k1 + 3u;
    TF_G(17, 29, 16, 24) x0 += k1; x1 += k2 + 4u;
    TF_G(13, 15, 26, 6)  x0 += k2; x1 += k0 + 5u;
#undef TF_G
#undef TF_R
    o0 = x0; o1 = x1;
}
__device__ __forceinline__ float jax_normal_from_bits(uint32_t bits) {
    float u1 = __uint_as_float(0x3f800000u | (bits >> 9)) - 1.0f;
    const float lo = __uint_as_float(0xBF7FFFFFu);
    float u = __fadd_rn(__fmul_rn(u1, 2.0f), lo);
    u = fmaxf(u, lo);
    float w = -log1pf(-__fmul_rn(u, u));
    float p;
    if (w < 5.0f) {
        w = __fsub_rn(w, 2.5f);
        p = 2.81022636e-08f;
        p = __fmaf_rn(p, w, 3.43273939e-07f);
        p = __fmaf_rn(p, w, -3.5233877e-06f);
        p = __fmaf_rn(p, w, -4.39150654e-06f);
        p = __fmaf_rn(p, w, 0.00021858087f);
        p = __fmaf_rn(p, w, -0.00125372503f);
        p = __fmaf_rn(p, w, -0.00417768164f);
        p = __fmaf_rn(p, w, 0.246640727f);
        p = __fmaf_rn(p, w, 1.50140941f);
    } else {
        w = __fsub_rn(sqrtf(w), 3.0f);
        p = -0.000200214257f;
        p = __fmaf_rn(p, w, 0.000100950558f);
        p = __fmaf_rn(p, w, 0.00134934322f);
        p = __fmaf_rn(p, w, -0.00367342844f);
        p = __fmaf_rn(p, w, 0.00573950773f);
        p = __fmaf_rn(p, w, -0.0076224613f);
        p = __fmaf_rn(p, w, 0.00943887047f);
        p = __fmaf_rn(p, w, 1.00167406f);
        p = __fmaf_rn(p, w, 2.83297682f);
    }
    return __fmul_rn(__uint_as_float(0x3FB504F3u), __fmul_rn(p, u));
}
__device__ __forceinline__ float gen_normal_part(uint32_t k0, uint32_t k1, uint32_t i) {
    uint32_t o0, o1;
    threefry2x32(k0, k1, 0u, i, o0, o1);
    return jax_normal_from_bits(o0 ^ o1);
}

// ---- K1: router MLP ----
__global__ void __launch_bounds__(128) mlp_kernel(
    const float* __restrict__ phi, const float* __restrict__ w0, const float* __restrict__ b0,
    const float* __restrict__ w1, const float* __restrict__ b1, const float* __restrict__ w2,
    const float* __restrict__ b2, const float* __restrict__ noise_var, float* __restrict__ out) {
    __shared__ float sphi[512], sh[128], sh2[128], sl[12];
    int b = blockIdx.x, t = threadIdx.x;
    for (int d = t; d < 512; d += 128) sphi[d] = phi[b * 512 + d];
    __syncthreads();
    float a = 0.f;
    #pragma unroll 8
    for (int d = 0; d < 512; d++) a = __fmaf_rn(sphi[d], w0[d * 128 + t], a);
    sh[t] = fmaxf(__fadd_rn(a, b0[t]), 0.f);
    __syncthreads();
    float a2 = 0.f;
    #pragma unroll 8
    for (int i = 0; i < 128; i++) a2 = __fmaf_rn(sh[i], w1[i * 128 + t], a2);
    sh2[t] = fmaxf(__fadd_rn(a2, b1[t]), 0.f);
    __syncthreads();
    if (t < 12) {
        float l = 0.f;
        for (int i = 0; i < 128; i++) l = __fmaf_rn(sh2[i], w2[i * 12 + t], l);
        l = __fadd_rn(l, b2[t]);
        sl[t] = l;
        out[OFF_LOGITS + b * 12 + t] = l;
    }
    __syncthreads();
    if (t == 0) {
        float mx = sl[0]; int mi = 0;
        for (int j = 1; j < 12; j++) if (sl[j] > mx) { mx = sl[j]; mi = j; }
        float e[12], s = 0.f;
        for (int j = 0; j < 12; j++) { e[j] = expf(__fsub_rn(sl[j], mx)); s = __fadd_rn(s, e[j]); }
        for (int j = 0; j < 12; j++) out[OFF_PROBS + b * 12 + j] = __fdiv_rn(e[j], s);
        out[OFF_MODE + b] = (float)mi;
        g_expert[b] = mi / 3;
        g_phy[b] = mi % 3;
        if (b == 0) g_std = sqrtf(fmaxf(noise_var[0], 0.f));
    }
}

// ---- K2: fused row norms + bf16 conversion ----
__global__ void __launch_bounds__(256) sq_kernel(const float* __restrict__ H,
                                                 const float* __restrict__ cb) {
    int warp = (blockIdx.x * blockDim.x + threadIdx.x) >> 5;
    int lane = threadIdx.x & 31;
    const int TOT = NB * NN + NR * NK;
    if (warp >= TOT) return;
    bool isH = (warp < NB * NN);
    const float* src = isH ? (H + (size_t)warp * NCH) : (cb + (size_t)(warp - NB * NN) * NCH);
    __nv_bfloat16* dst = isH ? (g_Hb + (size_t)warp * NCH)
                             : (g_cbb + (size_t)(warp - NB * NN) * NCH);
    double s = 0.0;
    #pragma unroll
    for (int c = lane; c < NCH; c += 32) {
        float v = src[c];
        s += (double)__fmul_rn(v, v);
        dst[c] = __float2bfloat16_rn(v);
    }
    #pragma unroll
    for (int o = 16; o; o >>= 1) s += __shfl_down_sync(0xffffffffu, s, o);
    if (lane == 0) { if (isH) g_zsq[warp] = (float)s; else g_cbsq[warp - NB * NN] = (float)s; }
}

// ---- K3: A-in-register bf16 mma, 32-col B chunks double-buffered, x4 B ldmatrix ----
#define PADK 264
#define BBUF 16896
#define S3_CBSQ 0
#define S3_CNT 4096
#define S3_B 4608
#define S3_TOT 38400

__global__ void __launch_bounds__(256, 2) vqm_kernel() {
    extern __shared__ char smem[];
    float* cbsq_s = (float*)(smem + S3_CBSQ);
    int* cnt_s = (int*)(smem + S3_CNT);
    uint32_t bBase = smem_to_u32(smem + S3_B);

    int tid = threadIdx.x, wid = tid >> 5, lane = tid & 31;
    int row0 = blockIdx.x * 128;
    int r = g_expert[row0 >> 10];
    for (int j = tid; j < 1024; j += 256) cbsq_s[j] = g_cbsq[r * 1024 + j];
    if (tid < 128) cnt_s[tid] = 0;

    uint32_t afrag[64];
    int arow_in = (lane & 7) + ((lane >> 3) & 1) * 8;
    int acolsel = (lane >> 4) * 8;
    #pragma unroll
    for (int it = 0; it < 8; it++) {
        int u = it * 256 + tid; int rr = u >> 5, kk = (u & 31) * 8;
        cp16(bBase + (uint32_t)(rr * PADK + kk) * 2, g_Hb + (size_t)(row0 + rr) * 256 + kk);
    }
    asm volatile("cp.async.commit_group;");
    asm volatile("cp.async.wait_group 0;");
    __syncthreads();
    if (wid < 4) {
        int br = wid * 16 + arow_in;
        #pragma unroll
        for (int k16 = 0; k16 < 16; k16++)
            ldmx4(&afrag[k16 * 4], bBase + (uint32_t)(br * PADK + k16 * 16 + acolsel) * 2);
    }
    __syncthreads();
    #pragma unroll
    for (int it = 0; it < 8; it++) {
        int u = it * 256 + tid; int rr = u >> 5, kk = (u & 31) * 8;
        cp16(bBase + (uint32_t)(rr * PADK + kk) * 2, g_Hb + (size_t)(row0 + 64 + rr) * 256 + kk);
    }
    asm volatile("cp.async.commit_group;");
    asm volatile("cp.async.wait_group 0;");
    __syncthreads();
    if (wid >= 4) {
        int br = (wid - 4) * 16 + arow_in;
        #pragma unroll
        for (int k16 = 0; k16 < 16; k16++)
            ldmx4(&afrag[k16 * 4], bBase + (uint32_t)(br * PADK + k16 * 16 + acolsel) * 2);
    }
    __syncthreads();

    int q = lane >> 2, s4 = lane & 3;
    int rowA = wid * 16 + q, rowB = rowA + 8;
    float z1 = g_zsq[row0 + rowA], z2 = g_zsq[row0 + rowB];
    float rmin1 = FMAXV, rmin2 = FMAXV;
    int grp = lane >> 3, rowi = lane & 7;
    int b_row_off = (grp >> 1) * 8 + rowi;
    int b_col_off = (grp & 1) * 8;

    {
        uint32_t dst = bBase;
        #pragma unroll
        for (int it = 0; it < 4; it++) {
            int u = it * 256 + tid; int rr = u >> 5, kk = (u & 31) * 8;
            cp16(dst + (uint32_t)(rr * PADK + kk) * 2, g_cbb + (size_t)(r * 1024 + rr) * 256 + kk);
        }
        asm volatile("cp.async.commit_group;");
    }

    for (int ch = 0; ch < 32; ch++) {
        asm volatile("cp.async.wait_group 0;");
        __syncthreads();
        if (ch + 1 < 32) {
            uint32_t dst = bBase + (uint32_t)((ch + 1) & 1) * BBUF;
            #pragma unroll
            for (int it = 0; it < 4; it++) {
                int u = it * 256 + tid; int rr = u >> 5, kk = (u & 31) * 8;
                cp16(dst + (uint32_t)(rr * PADK + kk) * 2,
                     g_cbb + (size_t)(r * 1024 + (ch + 1) * 32 + rr) * 256 + kk);
            }
            asm volatile("cp.async.commit_group;");
        }
        uint32_t bcur = bBase + (uint32_t)(ch & 1) * BBUF;
        float acc[4][4];
        #pragma unroll
        for (int nf = 0; nf < 4; nf++)
            #pragma unroll
            for (int v = 0; v < 4; v++) acc[nf][v] = 0.f;
        #pragma unroll
        for (int k16 = 0; k16 < 16; k16++) {
            uint32_t bfr[8];
            #pragma unroll
            for (int np = 0; np < 2; np++)
                ldmx4(&bfr[np * 4],
                      bcur + (uint32_t)((np * 16 + b_row_off) * PADK + k16 * 16 + b_col_off) * 2);
            #pragma unroll
            for (int np = 0; np < 2; np++) {
                mma_bf16(acc[np * 2],     &afrag[k16 * 4], &bfr[np * 4]);
                mma_bf16(acc[np * 2 + 1], &afrag[k16 * 4], &bfr[np * 4 + 2]);
            }
        }
        float m1 = FMAXV, m2 = FMAXV;
        #pragma unroll
        for (int nf = 0; nf < 4; nf++) {
            #pragma unroll
            for (int v = 0; v < 2; v++) {
                float cq = cbsq_s[ch * 32 + nf * 8 + s4 * 2 + v];
                m1 = fminf(m1, __fmaf_rn(-2.f, acc[nf][v], __fadd_rn(z1, cq)));
                m2 = fminf(m2, __fmaf_rn(-2.f, acc[nf][v + 2], __fadd_rn(z2, cq)));
            }
        }
        m1 = fminf(m1, __shfl_xor_sync(0xffffffffu, m1, 1));
        m1 = fminf(m1, __shfl_xor_sync(0xffffffffu, m1, 2));
        m2 = fminf(m2, __shfl_xor_sync(0xffffffffu, m2, 1));
        m2 = fminf(m2, __shfl_xor_sync(0xffffffffu, m2, 2));
        rmin1 = fminf(rmin1, m1);
        rmin2 = fminf(rmin2, m2);
        float t1 = rmin1 + EPSF, t2 = rmin2 + EPSF;
        #pragma unroll
        for (int nf = 0; nf < 4; nf++) {
            #pragma unroll
            for (int v = 0; v < 2; v++) {
                int col = ch * 32 + nf * 8 + s4 * 2 + v;
                float cq = cbsq_s[col];
                float d1 = __fmaf_rn(-2.f, acc[nf][v], __fadd_rn(z1, cq));
                if (d1 <= t1) {
                    int pos = atomicAdd(&cnt_s[rowA], 1);
                    if (pos < CCAP) {
                        g_cand[(size_t)(row0 + rowA) * CCAP + pos] = col;
                        g_candd[(size_t)(row0 + rowA) * CCAP + pos] = d1;
                    }
                }
                float d2 = __fmaf_rn(-2.f, acc[nf][v + 2], __fadd_rn(z2, cq));
                if (d2 <= t2) {
                    int pos = atomicAdd(&cnt_s[rowB], 1);
                    if (pos < CCAP) {
                        g_cand[(size_t)(row0 + rowB) * CCAP + pos] = col;
                        g_candd[(size_t)(row0 + rowB) * CCAP + pos] = d2;
                    }
                }
            }
        }
    }
    __syncthreads();
    if (tid < 128) g_cc[row0 + tid] = cnt_s[tid];
}

// ---- K3b: re-rank + fused z_q/SSE/indices (vectorized epilogue) ----
__device__ __forceinline__ float seq_d(const float* __restrict__ z, const float* __restrict__ cr,
                                       float zsqv, float cbsqj) {
    float acc = 0.f;
    #pragma unroll 8
    for (int k = 0; k < 256; k++) acc = __fmaf_rn(z[k], cr[k], acc);
    return __fmaf_rn(-2.0f, acc, __fadd_rn(zsqv, cbsqj));
}
__global__ void __launch_bounds__(256) p2_kernel(const float* __restrict__ H,
                                                 const float* __restrict__ cb,
                                                 float* __restrict__ out) {
    __shared__ double ssep[8];
    int wid = threadIdx.x >> 5, lane = threadIdx.x & 31;
    int row = blockIdx.x * 8 + wid;
    int r = g_expert[row >> 10];
    const float* z = H + (size_t)row * 256;
    const float* cbase = cb + (size_t)r * 1024 * 256;
    const float* cbsq = g_cbsq + r * 1024;
    float zsqv = g_zsq[row];
    int c = g_cc[row];
    float best = FMAXV; int bestj = 0x7fffffff;
    if (c <= CCAP) {
        float dmin = FMAXV;
        for (int i0 = 0; i0 < c; i0 += 32) {
            float dv = (i0 + lane < c) ? g_candd[(size_t)row * CCAP + i0 + lane] : FMAXV;
            #pragma unroll
            for (int o = 16; o; o >>= 1) dv = fminf(dv, __shfl_xor_sync(0xffffffffu, dv, o));
            dmin = fminf(dmin, dv);
        }
        float thr = dmin + P2M;
        int nwin = 0, jwin = 0x7fffffff;
        for (int i0 = 0; i0 < c; i0 += 32) {
            int idx = i0 + lane;
            bool p = false; int j = 0x7fffffff;
            if (idx < c) {
                float dv = g_candd[(size_t)row * CCAP + idx];
                if (dv <= thr) { p = true; j = g_cand[(size_t)row * CCAP + idx]; }
            }
            uint32_t mask = __ballot_sync(0xffffffffu, p);
            nwin += __popc(mask);
            #pragma unroll
            for (int o = 16; o; o >>= 1) j = min(j, __shfl_xor_sync(0xffffffffu, j, o));
            jwin = min(jwin, j);
        }
        if (nwin == 1) {
            bestj = jwin;
        } else {
            for (int i0 = 0; i0 < c; i0 += 32) {
                int idx = i0 + lane;
                float dv = (idx < c) ? g_candd[(size_t)row * CCAP + idx] : FMAXV;
                int j = (idx < c) ? g_cand[(size_t)row * CCAP + idx] : 0x7fffffff;
                float ds = FMAXV;
                if (dv <= thr) ds = seq_d(z, cbase + (size_t)j * 256, zsqv, cbsq[j]);
                else j = 0x7fffffff;
                #pragma unroll
                for (int o = 16; o; o >>= 1) {
                    float od = __shfl_xor_sync(0xffffffffu, ds, o);
                    int oj = __shfl_xor_sync(0xffffffffu, j, o);
                    if (od < ds || (od == ds && oj < j)) { ds = od; j = oj; }
                }
                if (ds < best || (ds == best && j < bestj)) { best = ds; bestj = j; }
            }
        }
    } else {
        for (int j0 = 0; j0 < 1024; j0 += 32) {
            int j = j0 + lane;
            float ds = seq_d(z, cbase + (size_t)j * 256, zsqv, cbsq[j]);
            #pragma unroll
            for (int o = 16; o; o >>= 1) {
                float od = __shfl_xor_sync(0xffffffffu, ds, o);
                int oj = __shfl_xor_sync(0xffffffffu, j, o);
                if (od < ds || (od == ds && oj < j)) { ds = od; j = oj; }
            }
            if (ds < best || (ds == best && j < bestj)) { best = ds; bestj = j; }
        }
    }
    if (lane == 0) {
        g_indices[row] = bestj;
        out[OFF_IND + row] = (float)bestj;
    }
    bestj = __shfl_sync(0xffffffffu, bestj, 0);
    // vectorized fused z_q / SSE (float4 x2 per lane)
    const float4* z4 = reinterpret_cast<const float4*>(z);
    const float4* c4 = reinterpret_cast<const float4*>(cbase + (size_t)bestj * 256);
    float4* o4 = reinterpret_cast<float4*>(out + OFF_ZQ + (size_t)row * 256);
    double acc = 0.0;
    #pragma unroll
    for (int t = 0; t < 2; t++) {
        int k4 = lane + t * 32;
        float4 hv = z4[k4];
        float4 cv = c4[k4];
        float dx = __fsub_rn(cv.x, hv.x), dy = __fsub_rn(cv.y, hv.y);
        float dz = __fsub_rn(cv.z, hv.z), dw = __fsub_rn(cv.w, hv.w);
        o4[k4] = make_float4(__fadd_rn(hv.x, dx), __fadd_rn(hv.y, dy),
                             __fadd_rn(hv.z, dz), __fadd_rn(hv.w, dw));
        acc += (double)__fmul_rn(dx, dx) + (double)__fmul_rn(dy, dy)
             + (double)__fmul_rn(dz, dz) + (double)__fmul_rn(dw, dw);
    }
    #pragma unroll
    for (int o = 16; o; o >>= 1) acc += __shfl_down_sync(0xffffffffu, acc, o);
    if (lane == 0) ssep[wid] = acc;
    __syncthreads();
    if (threadIdx.x == 0) {
        double s = 0.0;
        #pragma unroll
        for (int w = 0; w < 8; w++) s += ssep[w];
        g_ssep[blockIdx.x] = s;
    }
}

// ---- K5: QAM channel (symbol-parallel) ----
__global__ void __launch_bounds__(256) channel_kernel() {
    int b = blockIdx.x;
    int m = g_phy[b];
    int bps = (m == 0) ? 2 : (m == 1) ? 4 : 6;
    int n_sym = PADB / bps;
    int mside = (m == 0) ? 2 : (m == 1) ? 4 : 8;
    int M = mside * mside;
    float std_ = g_std;
    __shared__ float cx[64], cy[64];
    __shared__ uint32_t skey[2];
    if (threadIdx.x < M) {
        double mean = (m == 0) ? 2.0 : (m == 1) ? 10.0 : 42.0;
        double norm = sqrt(mean + 1e-9);
        int i = threadIdx.x / mside, j = threadIdx.x % mside;
        cx[threadIdx.x] = (float)((double)(-(mside - 1) + 2 * i) / norm);
        cy[threadIdx.x] = (float)((double)(-(mside - 1) + 2 * j) / norm);
    }
    if (threadIdx.x == 0) {
        uint32_t o0, o1;
        threefry2x32(0u, 42u, 0u, (uint32_t)m, o0, o1);
        skey[0] = o0; skey[1] = o1;
    }
    __syncthreads();
    int s = blockIdx.y * 256 + threadIdx.x;
    if (s >= n_sym) return;
    uint32_t k0 = skey[0], k1 = skey[1];
    const int* idxrow = g_indices + b * NN;
    uint8_t* bitrow = g_bits + b * PADB;
    int p0 = s * bps, sym = 0;
    for (int j = 0; j < bps; j++) {
        int p = p0 + j, bit = 0;
        if (p < TOTB) bit = (idxrow[p / 10] >> (9 - p % 10)) & 1;
        sym = (sym << 1) | bit;
    }
    float tx0 = cx[sym], tx1 = cy[sym];
    uint32_t i0 = (uint32_t)(b * n_sym + s) * 2u;
    float rx0 = __fadd_rn(tx0, __fmul_rn(std_, gen_normal_part(k0, k1, i0)));
    float rx1 = __fadd_rn(tx1, __fmul_rn(std_, gen_normal_part(k0, k1, i0 + 1u)));
    float best = FMAXV; int bi = 0;
    for (int k = 0; k < M; k++) {
        float dx = __fsub_rn(rx0, cx[k]), dy = __fsub_rn(rx1, cy[k]);
        float d = __fadd_rn(__fmul_rn(dx, dx), __fmul_rn(dy, dy));
        if (d < best) { best = d; bi = k; }
    }
    for (int j = 0; j < bps; j++)
        bitrow[p0 + j] = (uint8_t)((bi >> (bps - 1 - j)) & 1);
}

// ---- K6: idx_hat + H_hat + vq_loss ----
__global__ void __launch_bounds__(256) final_kernel(const float* __restrict__ H,
                                                    const float* __restrict__ cb,
                                                    float* __restrict__ out) {
    __shared__ int sidx[16];
    __shared__ double sred[256];
    int t = threadIdx.x;
    int row0 = blockIdx.x * 16;
    int b = row0 >> 10;
    int r = g_expert[b];
    if (t < 16) {
        int row = row0 + t;
        int n = row & (NN - 1);
        const uint8_t* bt = g_bits + b * PADB + n * 10;
        int v = 0;
        #pragma unroll
        for (int j = 0; j < 10; j++) v = (v << 1) | bt[j];
        if (v > NK - 1) v = NK - 1;
        sidx[t] = v;
        out[OFF_IDXHAT + row] = (float)v;
    }
    __syncthreads();
    #pragma unroll
    for (int it = 0; it < 4; it++) {
        int qid = it * 256 + t;
        int rl = qid >> 6, qq = qid & 63;
        size_t row = (size_t)row0 + rl;
        float4 h = reinterpret_cast<const float4*>(H)[row * 64 + qq];
        float4 c = reinterpret_cast<const float4*>(cb)[((size_t)r * 1024 + sidx[rl]) * 64 + qq];
        reinterpret_cast<float4*>(out + OFF_HHAT)[row * 64 + qq] =
            make_float4(__fadd_rn(h.x, __fsub_rn(c.x, h.x)), __fadd_rn(h.y, __fsub_rn(c.y, h.y)),
                        __fadd_rn(h.z, __fsub_rn(c.z, h.z)), __fadd_rn(h.w, __fsub_rn(c.w, h.w)));
    }
    if (blockIdx.x == 0) {
        double s = 0.0;
        for (int i = t; i < 8192; i += 256) s += g_ssep[i];
        sred[t] = s;
        __syncthreads();
        for (int st = 128; st; st >>= 1) {
            if (t < st) sred[t] += sred[t + st];
            __syncthreads();
        }
        if (t == 0) {
            double denom = (double)NB * (double)NN * (double)NCH * (double)NCH;
            out[OFF_VQ] = (float)(1.25 * sred[0] / denom);
        }
    }
}

// ---- launch ----
extern "C" void kernel_launch(void* const* d_in, const int* in_sizes, int n_in,
                              void* d_out, int out_size) {
    const float* H         = (const float*)d_in[0];
    const float* phi       = (const float*)d_in[1];
    const float* w0        = (const float*)d_in[2];
    const float* b0        = (const float*)d_in[3];
    const float* w1        = (const float*)d_in[4];
    const float* b1        = (const float*)d_in[5];
    const float* w2        = (const float*)d_in[6];
    const float* b2        = (const float*)d_in[7];
    const float* codebooks = (const float*)d_in[8];
    const float* noise_var = (const float*)d_in[9];
    float* out = (float*)d_out;

    cudaFuncSetAttribute(vqm_kernel, cudaFuncAttributeMaxDynamicSharedMemorySize, S3_TOT);

    mlp_kernel<<<NB, 128>>>(phi, w0, b0, w1, b1, w2, b2, noise_var, out);
    sq_kernel<<<(NB * NN + NR * NK + 7) / 8, 256>>>(H, codebooks);
    vqm_kernel<<<NB * NN / 128, 256, S3_TOT>>>();
    p2_kernel<<<NB * NN / 8, 256>>>(H, codebooks, out);
    channel_kernel<<<dim3(NB, 21), 256>>>();
    final_kernel<<<NB * NN / 16, 256>>>(H, codebooks, out);
}

// round 15
// speedup vs baseline: 1.0208x; 1.0208x over previous
#include <cuda_runtime.h>
#include <cuda_bf16.h>
#include <stdint.h>
#include <math.h>

#define NB 64
#define NN 1024
#define NCH 256
#define NR 4
#define NK 1024
#define TOTB 10240
#define PADB 10248
#define EPSF 0.25f
#define P2M  0.1f
#define CCAP 128
#define FMAXV 3.402823466e+38f

#define OFF_HHAT   0LL
#define OFF_ZQ     16777216LL
#define OFF_IND    33554432LL
#define OFF_IDXHAT 33619968LL
#define OFF_VQ     33685504LL
#define OFF_LOGITS 33685505LL
#define OFF_PROBS  33686273LL
#define OFF_MODE   33687041LL

__device__ int     g_expert[NB];
__device__ int     g_phy[NB];
__device__ float   g_std;
__device__ float   g_zsq[NB * NN];
__device__ float   g_cbsq[NR * NK];
__device__ int     g_indices[NB * NN];
__device__ uint8_t g_bits[NB * PADB];
__device__ double  g_sse;
__device__ __align__(16) __nv_bfloat16 g_Hb[NB * NN * NCH];
__device__ __align__(16) __nv_bfloat16 g_cbb[NR * NK * NCH];
__device__ int   g_cand[(size_t)NB * NN * CCAP];
__device__ float g_candd[(size_t)NB * NN * CCAP];
__device__ int   g_cc[NB * NN];

// ---- helpers ----
__device__ __forceinline__ uint32_t smem_to_u32(const void* p) {
    uint32_t a;
    asm("{ .reg .u64 t; cvta.to.shared.u64 t, %1; cvt.u32.u64 %0, t; }" : "=r"(a) : "l"(p));
    return a;
}
__device__ __forceinline__ void ldmx4(uint32_t* r, uint32_t addr) {
    asm volatile("ldmatrix.sync.aligned.m8n8.x4.shared.b16 {%0,%1,%2,%3}, [%4];"
        : "=r"(r[0]), "=r"(r[1]), "=r"(r[2]), "=r"(r[3]) : "r"(addr));
}
__device__ __forceinline__ void mma_bf16(float* c, const uint32_t* a, const uint32_t* b) {
    asm volatile("mma.sync.aligned.m16n8k16.row.col.f32.bf16.bf16.f32 "
        "{%0,%1,%2,%3}, {%4,%5,%6,%7}, {%8,%9}, {%0,%1,%2,%3};"
        : "+f"(c[0]), "+f"(c[1]), "+f"(c[2]), "+f"(c[3])
        : "r"(a[0]), "r"(a[1]), "r"(a[2]), "r"(a[3]), "r"(b[0]), "r"(b[1]));
}
__device__ __forceinline__ void cp16(uint32_t dst, const void* src) {
    asm volatile("cp.async.cg.shared.global [%0], [%1], 16;" :: "r"(dst), "l"(src));
}

// ---- threefry (JAX) ----
__device__ __forceinline__ uint32_t rotl32(uint32_t x, int r) { return (x << r) | (x >> (32 - r)); }
__device__ __forceinline__ void threefry2x32(uint32_t k0, uint32_t k1, uint32_t x0, uint32_t x1,
                                             uint32_t& o0, uint32_t& o1) {
    uint32_t k2 = k0 ^ k1 ^ 0x1BD11BDAu;
    x0 += k0; x1 += k1;
#define TF_R(a) x0 += x1; x1 = rotl32(x1, a); x1 ^= x0;
#define TF_G(a,b,c,d) TF_R(a) TF_R(b) TF_R(c) TF_R(d)
    TF_G(13, 15, 26, 6)  x0 += k1; x1 += k2 + 1u;
    TF_G(17, 29, 16, 24) x0 += k2; x1 += k0 + 2u;
    TF_G(13, 15, 26, 6)  x0 += k0; x1 += k1 + 3u;
    TF_G(17, 29, 16, 24) x0 += k1; x1 += k2 + 4u;
    TF_G(13, 15, 26, 6)  x0 += k2; x1 += k0 + 5u;
#undef TF_G
#undef TF_R
    o0 = x0; o1 = x1;
}
__device__ __forceinline__ float jax_normal_from_bits(uint32_t bits) {
    float u1 = __uint_as_float(0x3f800000u | (bits >> 9)) - 1.0f;
    const float lo = __uint_as_float(0xBF7FFFFFu);
    float u = __fadd_rn(__fmul_rn(u1, 2.0f), lo);
    u = fmaxf(u, lo);
    float w = -log1pf(-__fmul_rn(u, u));
    float p;
    if (w < 5.0f) {
        w = __fsub_rn(w, 2.5f);
        p = 2.81022636e-08f;
        p = __fmaf_rn(p, w, 3.43273939e-07f);
        p = __fmaf_rn(p, w, -3.5233877e-06f);
        p = __fmaf_rn(p, w, -4.39150654e-06f);
        p = __fmaf_rn(p, w, 0.00021858087f);
        p = __fmaf_rn(p, w, -0.00125372503f);
        p = __fmaf_rn(p, w, -0.00417768164f);
        p = __fmaf_rn(p, w, 0.246640727f);
        p = __fmaf_rn(p, w, 1.50140941f);
    } else {
        w = __fsub_rn(sqrtf(w), 3.0f);
        p = -0.000200214257f;
        p = __fmaf_rn(p, w, 0.000100950558f);
        p = __fmaf_rn(p, w, 0.00134934322f);
        p = __fmaf_rn(p, w, -0.00367342844f);
        p = __fmaf_rn(p, w, 0.00573950773f);
        p = __fmaf_rn(p, w, -0.0076224613f);
        p = __fmaf_rn(p, w, 0.00943887047f);
        p = __fmaf_rn(p, w, 1.00167406f);
        p = __fmaf_rn(p, w, 2.83297682f);
    }
    return __fmul_rn(__uint_as_float(0x3FB504F3u), __fmul_rn(p, u));
}
__device__ __forceinline__ float gen_normal_part(uint32_t k0, uint32_t k1, uint32_t i) {
    uint32_t o0, o1;
    threefry2x32(k0, k1, 0u, i, o0, o1);
    return jax_normal_from_bits(o0 ^ o1);
}

// ---- K1: router MLP ----
__global__ void __launch_bounds__(128) mlp_kernel(
    const float* __restrict__ phi, const float* __restrict__ w0, const float* __restrict__ b0,
    const float* __restrict__ w1, const float* __restrict__ b1, const float* __restrict__ w2,
    const float* __restrict__ b2, const float* __restrict__ noise_var, float* __restrict__ out) {
    __shared__ float sphi[512], sh[128], sh2[128], sl[12];
    int b = blockIdx.x, t = threadIdx.x;
    if (b == 0 && t == 0) g_sse = 0.0;
    for (int d = t; d < 512; d += 128) sphi[d] = phi[b * 512 + d];
    __syncthreads();
    float a = 0.f;
    #pragma unroll 8
    for (int d = 0; d < 512; d++) a = __fmaf_rn(sphi[d], w0[d * 128 + t], a);
    sh[t] = fmaxf(__fadd_rn(a, b0[t]), 0.f);
    __syncthreads();
    float a2 = 0.f;
    #pragma unroll 8
    for (int i = 0; i < 128; i++) a2 = __fmaf_rn(sh[i], w1[i * 128 + t], a2);
    sh2[t] = fmaxf(__fadd_rn(a2, b1[t]), 0.f);
    __syncthreads();
    if (t < 12) {
        float l = 0.f;
        for (int i = 0; i < 128; i++) l = __fmaf_rn(sh2[i], w2[i * 12 + t], l);
        l = __fadd_rn(l, b2[t]);
        sl[t] = l;
        out[OFF_LOGITS + b * 12 + t] = l;
    }
    __syncthreads();
    if (t == 0) {
        float mx = sl[0]; int mi = 0;
        for (int j = 1; j < 12; j++) if (sl[j] > mx) { mx = sl[j]; mi = j; }
        float e[12], s = 0.f;
        for (int j = 0; j < 12; j++) { e[j] = expf(__fsub_rn(sl[j], mx)); s = __fadd_rn(s, e[j]); }
        for (int j = 0; j < 12; j++) out[OFF_PROBS + b * 12 + j] = __fdiv_rn(e[j], s);
        out[OFF_MODE + b] = (float)mi;
        g_expert[b] = mi / 3;
        g_phy[b] = mi % 3;
        if (b == 0) g_std = sqrtf(fmaxf(noise_var[0], 0.f));
    }
}

// ---- K2: fused row norms + bf16 conversion ----
__global__ void __launch_bounds__(256) sq_kernel(const float* __restrict__ H,
                                                 const float* __restrict__ cb) {
    int warp = (blockIdx.x * blockDim.x + threadIdx.x) >> 5;
    int lane = threadIdx.x & 31;
    const int TOT = NB * NN + NR * NK;
    if (warp >= TOT) return;
    bool isH = (warp < NB * NN);
    const float* src = isH ? (H + (size_t)warp * NCH) : (cb + (size_t)(warp - NB * NN) * NCH);
    __nv_bfloat16* dst = isH ? (g_Hb + (size_t)warp * NCH)
                             : (g_cbb + (size_t)(warp - NB * NN) * NCH);
    double s = 0.0;
    #pragma unroll
    for (int c = lane; c < NCH; c += 32) {
        float v = src[c];
        s += (double)__fmul_rn(v, v);
        dst[c] = __float2bfloat16_rn(v);
    }
    #pragma unroll
    for (int o = 16; o; o >>= 1) s += __shfl_down_sync(0xffffffffu, s, o);
    if (lane == 0) { if (isH) g_zsq[warp] = (float)s; else g_cbsq[warp - NB * NN] = (float)s; }
}

// ---- K3: A-in-register bf16 mma (validated) ----
#define PADK 264
#define BBUF 16896
#define S3_CBSQ 0
#define S3_CNT 4096
#define S3_B 4608
#define S3_TOT 38400

__global__ void __launch_bounds__(256, 2) vqm_kernel() {
    extern __shared__ char smem[];
    float* cbsq_s = (float*)(smem + S3_CBSQ);
    int* cnt_s = (int*)(smem + S3_CNT);
    uint32_t bBase = smem_to_u32(smem + S3_B);

    int tid = threadIdx.x, wid = tid >> 5, lane = tid & 31;
    int row0 = blockIdx.x * 128;
    int r = g_expert[row0 >> 10];
    for (int j = tid; j < 1024; j += 256) cbsq_s[j] = g_cbsq[r * 1024 + j];
    if (tid < 128) cnt_s[tid] = 0;

    uint32_t afrag[64];
    int arow_in = (lane & 7) + ((lane >> 3) & 1) * 8;
    int acolsel = (lane >> 4) * 8;
    #pragma unroll
    for (int it = 0; it < 8; it++) {
        int u = it * 256 + tid; int rr = u >> 5, kk = (u & 31) * 8;
        cp16(bBase + (uint32_t)(rr * PADK + kk) * 2, g_Hb + (size_t)(row0 + rr) * 256 + kk);
    }
    asm volatile("cp.async.commit_group;");
    asm volatile("cp.async.wait_group 0;");
    __syncthreads();
    if (wid < 4) {
        int br = wid * 16 + arow_in;
        #pragma unroll
        for (int k16 = 0; k16 < 16; k16++)
            ldmx4(&afrag[k16 * 4], bBase + (uint32_t)(br * PADK + k16 * 16 + acolsel) * 2);
    }
    __syncthreads();
    #pragma unroll
    for (int it = 0; it < 8; it++) {
        int u = it * 256 + tid; int rr = u >> 5, kk = (u & 31) * 8;
        cp16(bBase + (uint32_t)(rr * PADK + kk) * 2, g_Hb + (size_t)(row0 + 64 + rr) * 256 + kk);
    }
    asm volatile("cp.async.commit_group;");
    asm volatile("cp.async.wait_group 0;");
    __syncthreads();
    if (wid >= 4) {
        int br = (wid - 4) * 16 + arow_in;
        #pragma unroll
        for (int k16 = 0; k16 < 16; k16++)
            ldmx4(&afrag[k16 * 4], bBase + (uint32_t)(br * PADK + k16 * 16 + acolsel) * 2);
    }
    __syncthreads();

    int q = lane >> 2, s4 = lane & 3;
    int rowA = wid * 16 + q, rowB = rowA + 8;
    float z1 = g_zsq[row0 + rowA], z2 = g_zsq[row0 + rowB];
    float rmin1 = FMAXV, rmin2 = FMAXV;
    int grp = lane >> 3, rowi = lane & 7;
    int b_row_off = (grp >> 1) * 8 + rowi;
    int b_col_off = (grp & 1) * 8;

    {
        uint32_t dst = bBase;
        #pragma unroll
        for (int it = 0; it < 4; it++) {
            int u = it * 256 + tid; int rr = u >> 5, kk = (u & 31) * 8;
            cp16(dst + (uint32_t)(rr * PADK + kk) * 2, g_cbb + (size_t)(r * 1024 + rr) * 256 + kk);
        }
        asm volatile("cp.async.commit_group;");
    }

    for (int ch = 0; ch < 32; ch++) {
        asm volatile("cp.async.wait_group 0;");
        __syncthreads();
        if (ch + 1 < 32) {
            uint32_t dst = bBase + (uint32_t)((ch + 1) & 1) * BBUF;
            #pragma unroll
            for (int it = 0; it < 4; it++) {
                int u = it * 256 + tid; int rr = u >> 5, kk = (u & 31) * 8;
                cp16(dst + (uint32_t)(rr * PADK + kk) * 2,
                     g_cbb + (size_t)(r * 1024 + (ch + 1) * 32 + rr) * 256 + kk);
            }
            asm volatile("cp.async.commit_group;");
        }
        uint32_t bcur = bBase + (uint32_t)(ch & 1) * BBUF;
        float acc[4][4];
        #pragma unroll
        for (int nf = 0; nf < 4; nf++)
            #pragma unroll
            for (int v = 0; v < 4; v++) acc[nf][v] = 0.f;
        #pragma unroll
        for (int k16 = 0; k16 < 16; k16++) {
            uint32_t bfr[8];
            #pragma unroll
            for (int np = 0; np < 2; np++)
                ldmx4(&bfr[np * 4],
                      bcur + (uint32_t)((np * 16 + b_row_off) * PADK + k16 * 16 + b_col_off) * 2);
            #pragma unroll
            for (int np = 0; np < 2; np++) {
                mma_bf16(acc[np * 2],     &afrag[k16 * 4], &bfr[np * 4]);
                mma_bf16(acc[np * 2 + 1], &afrag[k16 * 4], &bfr[np * 4 + 2]);
            }
        }
        float m1 = FMAXV, m2 = FMAXV;
        #pragma unroll
        for (int nf = 0; nf < 4; nf++) {
            #pragma unroll
            for (int v = 0; v < 2; v++) {
                float cq = cbsq_s[ch * 32 + nf * 8 + s4 * 2 + v];
                m1 = fminf(m1, __fmaf_rn(-2.f, acc[nf][v], __fadd_rn(z1, cq)));
                m2 = fminf(m2, __fmaf_rn(-2.f, acc[nf][v + 2], __fadd_rn(z2, cq)));
            }
        }
        m1 = fminf(m1, __shfl_xor_sync(0xffffffffu, m1, 1));
        m1 = fminf(m1, __shfl_xor_sync(0xffffffffu, m1, 2));
        m2 = fminf(m2, __shfl_xor_sync(0xffffffffu, m2, 1));
        m2 = fminf(m2, __shfl_xor_sync(0xffffffffu, m2, 2));
        rmin1 = fminf(rmin1, m1);
        rmin2 = fminf(rmin2, m2);
        float t1 = rmin1 + EPSF, t2 = rmin2 + EPSF;
        #pragma unroll
        for (int nf = 0; nf < 4; nf++) {
            #pragma unroll
            for (int v = 0; v < 2; v++) {
                int col = ch * 32 + nf * 8 + s4 * 2 + v;
                float cq = cbsq_s[col];
                float d1 = __fmaf_rn(-2.f, acc[nf][v], __fadd_rn(z1, cq));
                if (d1 <= t1) {
                    int pos = atomicAdd(&cnt_s[rowA], 1);
                    if (pos < CCAP) {
                        g_cand[(size_t)(row0 + rowA) * CCAP + pos] = col;
                        g_candd[(size_t)(row0 + rowA) * CCAP + pos] = d1;
                    }
                }
                float d2 = __fmaf_rn(-2.f, acc[nf][v + 2], __fadd_rn(z2, cq));
                if (d2 <= t2) {
                    int pos = atomicAdd(&cnt_s[rowB], 1);
                    if (pos < CCAP) {
                        g_cand[(size_t)(row0 + rowB) * CCAP + pos] = col;
                        g_candd[(size_t)(row0 + rowB) * CCAP + pos] = d2;
                    }
                }
            }
        }
    }
    __syncthreads();
    if (tid < 128) g_cc[row0 + tid] = cnt_s[tid];
}

// ---- K3b: re-rank (indices ONLY — epilogue moved to final_kernel) ----
__device__ __forceinline__ float seq_d(const float* __restrict__ z, const float* __restrict__ cr,
                                       float zsqv, float cbsqj) {
    float acc = 0.f;
    #pragma unroll 8
    for (int k = 0; k < 256; k++) acc = __fmaf_rn(z[k], cr[k], acc);
    return __fmaf_rn(-2.0f, acc, __fadd_rn(zsqv, cbsqj));
}
__global__ void __launch_bounds__(256) p2_kernel(const float* __restrict__ H,
                                                 const float* __restrict__ cb,
                                                 float* __restrict__ out) {
    int wid = threadIdx.x >> 5, lane = threadIdx.x & 31;
    int row = blockIdx.x * 8 + wid;
    int r = g_expert[row >> 10];
    const float* z = H + (size_t)row * 256;
    const float* cbase = cb + (size_t)r * 1024 * 256;
    const float* cbsq = g_cbsq + r * 1024;
    float zsqv = g_zsq[row];
    int c = g_cc[row];
    float best = FMAXV; int bestj = 0x7fffffff;
    if (c <= CCAP) {
        float dmin = FMAXV;
        for (int i0 = 0; i0 < c; i0 += 32) {
            float dv = (i0 + lane < c) ? g_candd[(size_t)row * CCAP + i0 + lane] : FMAXV;
            #pragma unroll
            for (int o = 16; o; o >>= 1) dv = fminf(dv, __shfl_xor_sync(0xffffffffu, dv, o));
            dmin = fminf(dmin, dv);
        }
        float thr = dmin + P2M;
        int nwin = 0, jwin = 0x7fffffff;
        for (int i0 = 0; i0 < c; i0 += 32) {
            int idx = i0 + lane;
            bool p = false; int j = 0x7fffffff;
            if (idx < c) {
                float dv = g_candd[(size_t)row * CCAP + idx];
                if (dv <= thr) { p = true; j = g_cand[(size_t)row * CCAP + idx]; }
            }
            uint32_t mask = __ballot_sync(0xffffffffu, p);
            nwin += __popc(mask);
            #pragma unroll
            for (int o = 16; o; o >>= 1) j = min(j, __shfl_xor_sync(0xffffffffu, j, o));
            jwin = min(jwin, j);
        }
        if (nwin == 1) {
            bestj = jwin;
        } else {
            for (int i0 = 0; i0 < c; i0 += 32) {
                int idx = i0 + lane;
                float dv = (idx < c) ? g_candd[(size_t)row * CCAP + idx] : FMAXV;
                int j = (idx < c) ? g_cand[(size_t)row * CCAP + idx] : 0x7fffffff;
                float ds = FMAXV;
                if (dv <= thr) ds = seq_d(z, cbase + (size_t)j * 256, zsqv, cbsq[j]);
                else j = 0x7fffffff;
                #pragma unroll
                for (int o = 16; o; o >>= 1) {
                    float od = __shfl_xor_sync(0xffffffffu, ds, o);
                    int oj = __shfl_xor_sync(0xffffffffu, j, o);
                    if (od < ds || (od == ds && oj < j)) { ds = od; j = oj; }
                }
                if (ds < best || (ds == best && j < bestj)) { best = ds; bestj = j; }
            }
        }
    } else {
        for (int j0 = 0; j0 < 1024; j0 += 32) {
            int j = j0 + lane;
            float ds = seq_d(z, cbase + (size_t)j * 256, zsqv, cbsq[j]);
            #pragma unroll
            for (int o = 16; o; o >>= 1) {
                float od = __shfl_xor_sync(0xffffffffu, ds, o);
                int oj = __shfl_xor_sync(0xffffffffu, j, o);
                if (od < ds || (od == ds && oj < j)) { ds = od; j = oj; }
            }
            if (ds < best || (ds == best && j < bestj)) { best = ds; bestj = j; }
        }
    }
    if (lane == 0) {
        g_indices[row] = bestj;
        out[OFF_IND + row] = (float)bestj;
    }
}

// ---- K5: QAM channel (symbol-parallel) ----
__global__ void __launch_bounds__(256) channel_kernel() {
    int b = blockIdx.x;
    int m = g_phy[b];
    int bps = (m == 0) ? 2 : (m == 1) ? 4 : 6;
    int n_sym = PADB / bps;
    int mside = (m == 0) ? 2 : (m == 1) ? 4 : 8;
    int M = mside * mside;
    float std_ = g_std;
    __shared__ float cx[64], cy[64];
    __shared__ uint32_t skey[2];
    if (threadIdx.x < M) {
        double mean = (m == 0) ? 2.0 : (m == 1) ? 10.0 : 42.0;
        double norm = sqrt(mean + 1e-9);
        int i = threadIdx.x / mside, j = threadIdx.x % mside;
        cx[threadIdx.x] = (float)((double)(-(mside - 1) + 2 * i) / norm);
        cy[threadIdx.x] = (float)((double)(-(mside - 1) + 2 * j) / norm);
    }
    if (threadIdx.x == 0) {
        uint32_t o0, o1;
        threefry2x32(0u, 42u, 0u, (uint32_t)m, o0, o1);
        skey[0] = o0; skey[1] = o1;
    }
    __syncthreads();
    int s = blockIdx.y * 256 + threadIdx.x;
    if (s >= n_sym) return;
    uint32_t k0 = skey[0], k1 = skey[1];
    const int* idxrow = g_indices + b * NN;
    uint8_t* bitrow = g_bits + b * PADB;
    int p0 = s * bps, sym = 0;
    for (int j = 0; j < bps; j++) {
        int p = p0 + j, bit = 0;
        if (p < TOTB) bit = (idxrow[p / 10] >> (9 - p % 10)) & 1;
        sym = (sym << 1) | bit;
    }
    float tx0 = cx[sym], tx1 = cy[sym];
    uint32_t i0 = (uint32_t)(b * n_sym + s) * 2u;
    float rx0 = __fadd_rn(tx0, __fmul_rn(std_, gen_normal_part(k0, k1, i0)));
    float rx1 = __fadd_rn(tx1, __fmul_rn(std_, gen_normal_part(k0, k1, i0 + 1u)));
    float best = FMAXV; int bi = 0;
    for (int k = 0; k < M; k++) {
        float dx = __fsub_rn(rx0, cx[k]), dy = __fsub_rn(rx1, cy[k]);
        float d = __fadd_rn(__fmul_rn(dx, dx), __fmul_rn(dy, dy));
        if (d < best) { best = d; bi = k; }
    }
    for (int j = 0; j < bps; j++)
        bitrow[p0 + j] = (uint8_t)((bi >> (bps - 1 - j)) & 1);
}

// ---- K6: fused idx_hat + H_hat + z_q + SSE (single H read) ----
__global__ void __launch_bounds__(256) final_kernel(const float* __restrict__ H,
                                                    const float* __restrict__ cb,
                                                    float* __restrict__ out) {
    __shared__ int sidx[16], sidxh[16];
    __shared__ double sred[256];
    int t = threadIdx.x;
    int row0 = blockIdx.x * 16;
    int b = row0 >> 10;
    int r = g_expert[b];
    if (t < 16) {
        int row = row0 + t;
        int n = row & (NN - 1);
        const uint8_t* bt = g_bits + b * PADB + n * 10;
        int v = 0;
        #pragma unroll
        for (int j = 0; j < 10; j++) v = (v << 1) | bt[j];
        if (v > NK - 1) v = NK - 1;
        sidxh[t] = v;
        out[OFF_IDXHAT + row] = (float)v;
        sidx[t] = g_indices[row];
    }
    __syncthreads();
    double acc = 0.0;
    #pragma unroll
    for (int it = 0; it < 4; it++) {
        int qid = it * 256 + t;
        int rl = qid >> 6, qq = qid & 63;
        size_t row = (size_t)row0 + rl;
        float4 h = reinterpret_cast<const float4*>(H)[row * 64 + qq];
        // H_hat from idx_hat
        float4 ch = reinterpret_cast<const float4*>(cb)[((size_t)r * 1024 + sidxh[rl]) * 64 + qq];
        reinterpret_cast<float4*>(out + OFF_HHAT)[row * 64 + qq] =
            make_float4(__fadd_rn(h.x, __fsub_rn(ch.x, h.x)), __fadd_rn(h.y, __fsub_rn(ch.y, h.y)),
                        __fadd_rn(h.z, __fsub_rn(ch.z, h.z)), __fadd_rn(h.w, __fsub_rn(ch.w, h.w)));
        // z_q from indices + SSE
        float4 cq = reinterpret_cast<const float4*>(cb)[((size_t)r * 1024 + sidx[rl]) * 64 + qq];
        float dx = __fsub_rn(cq.x, h.x), dy = __fsub_rn(cq.y, h.y);
        float dz = __fsub_rn(cq.z, h.z), dw = __fsub_rn(cq.w, h.w);
        reinterpret_cast<float4*>(out + OFF_ZQ)[row * 64 + qq] =
            make_float4(__fadd_rn(h.x, dx), __fadd_rn(h.y, dy), __fadd_rn(h.z, dz), __fadd_rn(h.w, dw));
        acc += (double)__fmul_rn(dx, dx) + (double)__fmul_rn(dy, dy)
             + (double)__fmul_rn(dz, dz) + (double)__fmul_rn(dw, dw);
    }
    sred[t] = acc;
    __syncthreads();
    for (int st = 128; st; st >>= 1) {
        if (t < st) sred[t] += sred[t + st];
        __syncthreads();
    }
    if (t == 0) atomicAdd(&g_sse, sred[0]);
}

// ---- K7: vq_loss writeback ----
__global__ void vqfin_kernel(float* __restrict__ out) {
    double denom = (double)NB * (double)NN * (double)NCH * (double)NCH;
    out[OFF_VQ] = (float)(1.25 * g_sse / denom);
}

// ---- launch ----
extern "C" void kernel_launch(void* const* d_in, const int* in_sizes, int n_in,
                              void* d_out, int out_size) {
    const float* H         = (const float*)d_in[0];
    const float* phi       = (const float*)d_in[1];
    const float* w0        = (const float*)d_in[2];
    const float* b0        = (const float*)d_in[3];
    const float* w1        = (const float*)d_in[4];
    const float* b1        = (const float*)d_in[5];
    const float* w2        = (const float*)d_in[6];
    const float* b2        = (const float*)d_in[7];
    const float* codebooks = (const float*)d_in[8];
    const float* noise_var = (const float*)d_in[9];
    float* out = (float*)d_out;

    cudaFuncSetAttribute(vqm_kernel, cudaFuncAttributeMaxDynamicSharedMemorySize, S3_TOT);

    mlp_kernel<<<NB, 128>>>(phi, w0, b0, w1, b1, w2, b2, noise_var, out);
    sq_kernel<<<(NB * NN + NR * NK + 7) / 8, 256>>>(H, codebooks);
    vqm_kernel<<<NB * NN / 128, 256, S3_TOT>>>();
    p2_kernel<<<NB * NN / 8, 256>>>(H, codebooks, out);
    channel_kernel<<<dim3(NB, 21), 256>>>();
    final_kernel<<<NB * NN / 16, 256>>>(H, codebooks, out);
    vqfin_kernel<<<1, 1>>>(out);
}